// round 10
// baseline (speedup 1.0000x reference)
#include <cuda_runtime.h>
#include <cuda_fp16.h>
#include <math.h>
#include <stdint.h>

#define D_HIDDEN 1024
#define D_INTER  4096
#define NE       8
#define NTOK     2048
#define NPAIR    (NTOK * 2)
#define GU_ROWS  8192

// per-buffer: AH 16K | AL 8K | BH 16K | BL 8K = 48K; two buffers
#define SM_AH 0
#define SM_AL 16384
#define SM_BH 24576
#define SM_BL 40960
#define SM_BUF 49152
#define SM_TOK 98304
#define SM_COEF 98816
#define SM_TOTAL 99328

__device__ __forceinline__ uint32_t smem_u32(const void* p) {
    uint32_t a;
    asm("{ .reg .u64 t; cvta.to.shared.u64 t, %1; cvt.u32.u64 %0, t; }" : "=r"(a) : "l"(p));
    return a;
}
#define LDSM_X4(r, addr) \
    asm volatile("ldmatrix.sync.aligned.m8n8.x4.shared.b16 {%0,%1,%2,%3}, [%4];" \
        : "=r"((r)[0]), "=r"((r)[1]), "=r"((r)[2]), "=r"((r)[3]) : "r"(addr))
#define MMAF16(c, a, b0, b1) \
    asm volatile("mma.sync.aligned.m16n8k16.row.col.f32.f16.f16.f32 " \
        "{%0,%1,%2,%3}, {%4,%5,%6,%7}, {%8,%9}, {%0,%1,%2,%3};" \
        : "+f"((c)[0]), "+f"((c)[1]), "+f"((c)[2]), "+f"((c)[3]) \
        : "r"((a)[0]), "r"((a)[1]), "r"((a)[2]), "r"((a)[3]), "r"(b0), "r"(b1))
#define MMAI8(c, a, b0, b1) \
    asm volatile("mma.sync.aligned.m16n8k32.row.col.s32.s8.s8.s32 " \
        "{%0,%1,%2,%3}, {%4,%5,%6,%7}, {%8,%9}, {%0,%1,%2,%3};" \
        : "+r"((c)[0]), "+r"((c)[1]), "+r"((c)[2]), "+r"((c)[3]) \
        : "r"((a)[0]), "r"((a)[1]), "r"((a)[2]), "r"((a)[3]), "r"(b0), "r"(b1))
#define CP16(dst, src) \
    asm volatile("cp.async.cg.shared.global [%0], [%1], 16;" :: "r"(dst), "l"(src))
#define CP_COMMIT() asm volatile("cp.async.commit_group;" ::: "memory")
#define CP_WAIT0()  asm volatile("cp.async.wait_group 0;" ::: "memory")

__device__ __forceinline__ uint32_t dq16(uint32_t byte, uint32_t adjc) {
    uint32_t n0 = byte & 15u, n1 = (byte >> 4) & 15u;
    uint32_t m0 = n0 & 7u, m1 = n1 & 7u;
    uint32_t b0 = (m0 == 0u) ? 0u : (adjc + ((m0 >= 2u) ? (m0 << 9) : 0u));
    uint32_t b1 = (m1 == 0u) ? 0u : (adjc + ((m1 >= 2u) ? (m1 << 9) : 0u));
    b0 |= (n0 & 8u) << 12;  b1 |= (n1 & 8u) << 12;
    return b0 | (b1 << 16);
}
__device__ __forceinline__ uint32_t dqi8(uint32_t nib, int sh) {
    int m2 = (int)((0xC8643210u >> ((nib & 7u) * 4)) & 15u);
    int v = (sh >= 0) ? (m2 << sh) : (m2 >> (-sh));
    return (uint32_t)((nib & 8u) ? -v : v) & 255u;
}

__device__ int   g_top_idx[NTOK][2];
__device__ float g_top_w[NTOK][2];
__device__ int   g_count[NE];
__device__ int   g_off[NE];
__device__ int   g_list[NE][NTOK];
__device__ float g_coefs[NE][NTOK];
__device__ unsigned short g_x_h[(size_t)NTOK * D_HIDDEN];
__device__ char  g_x_l[(size_t)NTOK * D_HIDDEN];
__device__ unsigned short g_act_h[(size_t)NPAIR * D_INTER];
__device__ char  g_act_l[(size_t)NPAIR * D_INTER];
__device__ uint4 g_gu_pack[(size_t)NE * GU_ROWS * 32];
__device__ uint4 g_dn_pack[(size_t)NE * D_HIDDEN * 128];
__device__ int   g_gu_smax[NE * GU_ROWS];
__device__ int   g_dn_smax[NE * D_HIDDEN];

__global__ void zero_kernel(float* __restrict__ out, int n) {
    int i = blockIdx.x * blockDim.x + threadIdx.x;
    if (i < n) out[i] = 0.0f;
}
__global__ void prep_x_kernel(const float* __restrict__ x) {
    int row = blockIdx.x;
    int c = threadIdx.x * 4;
    float4 f = *(const float4*)(x + (size_t)row * D_HIDDEN + c);
    float v[4] = {f.x, f.y, f.z, f.w};
    unsigned short h[4]; uint32_t l = 0;
#pragma unroll
    for (int i = 0; i < 4; i++) {
        __half hh = __float2half_rn(v[i]);
        h[i] = __half_as_ushort(hh);
        int q = __float2int_rn((v[i] - __half2float(hh)) * 65536.0f);
        q = max(-127, min(127, q));
        l |= ((uint32_t)q & 255u) << (i * 8);
    }
    uint2 ph;
    ph.x = (uint32_t)h[0] | ((uint32_t)h[1] << 16);
    ph.y = (uint32_t)h[2] | ((uint32_t)h[3] << 16);
    *(uint2*)(g_x_h + (size_t)row * D_HIDDEN + c) = ph;
    *(uint32_t*)(g_x_l + (size_t)row * D_HIDDEN + c) = l;
}
__global__ void pack_kernel(const int* __restrict__ src, uint4* __restrict__ dst) {
    size_t i = (size_t)blockIdx.x * 256 + threadIdx.x;
    const int4* s = (const int4*)src + i * 4;
    int4 a = s[0], b = s[1], c = s[2], d = s[3];
    uint4 o;
    o.x = (a.x & 255) | ((a.y & 255) << 8) | ((a.z & 255) << 16) | ((a.w & 255) << 24);
    o.y = (b.x & 255) | ((b.y & 255) << 8) | ((b.z & 255) << 16) | ((b.w & 255) << 24);
    o.z = (c.x & 255) | ((c.y & 255) << 8) | ((c.z & 255) << 16) | ((c.w & 255) << 24);
    o.w = (d.x & 255) | ((d.y & 255) << 8) | ((d.z & 255) << 16) | ((d.w & 255) << 24);
    dst[i] = o;
}
__global__ void smax_kernel(const int* __restrict__ sc, int* __restrict__ dst, int bpr) {
    int row = blockIdx.x * 8 + (threadIdx.x >> 5);
    int lane = threadIdx.x & 31;
    int m = 0;
    for (int i = lane; i < bpr; i += 32) m = max(m, sc[(size_t)row * bpr + i]);
#pragma unroll
    for (int o = 16; o > 0; o >>= 1) m = max(m, __shfl_xor_sync(0xffffffffu, m, o));
    if (lane == 0) dst[row] = m;
}
__global__ void router_kernel(const float* __restrict__ x,
                              const float* __restrict__ rw,
                              const float* __restrict__ rb) {
    int warp = threadIdx.x >> 5, lane = threadIdx.x & 31;
    int t = blockIdx.x * 8 + warp;
    if (t >= NTOK) return;
    float acc[NE];
#pragma unroll
    for (int e = 0; e < NE; e++) acc[e] = 0.0f;
    const float* xr = x + (size_t)t * D_HIDDEN;
    for (int k = lane; k < D_HIDDEN; k += 32) {
        float xv = xr[k];
#pragma unroll
        for (int e = 0; e < NE; e++) acc[e] += xv * rw[e * D_HIDDEN + k];
    }
#pragma unroll
    for (int e = 0; e < NE; e++)
#pragma unroll
        for (int o = 16; o > 0; o >>= 1) acc[e] += __shfl_xor_sync(0xffffffffu, acc[e], o);
    if (lane == 0) {
        float v[NE];
#pragma unroll
        for (int e = 0; e < NE; e++) v[e] = acc[e] + rb[e];
        int i0 = 0;
#pragma unroll
        for (int e = 1; e < NE; e++) if (v[e] > v[i0]) i0 = e;
        int i1 = -1;
#pragma unroll
        for (int e = 0; e < NE; e++) {
            if (e == i0) continue;
            if (i1 < 0 || v[e] > v[i1]) i1 = e;
        }
        float w1 = expf(v[i1] - v[i0]);
        float inv = 1.0f / (1.0f + w1);
        g_top_idx[t][0] = i0; g_top_idx[t][1] = i1;
        g_top_w[t][0] = inv;  g_top_w[t][1] = w1 * inv;
    }
}
__global__ void compact_kernel() {
    const int e = blockIdx.x, tid = threadIdx.x;
    __shared__ int scan[256];
    __shared__ int sbase;
    if (tid == 0) sbase = 0;
    __syncthreads();
    for (int c = 0; c < NTOK; c += 256) {
        int t = c + tid;
        int flag = (g_top_idx[t][0] == e) || (g_top_idx[t][1] == e);
        float coef = (g_top_idx[t][0] == e) ? g_top_w[t][0] : g_top_w[t][1];
        scan[tid] = flag;
        __syncthreads();
#pragma unroll
        for (int off = 1; off < 256; off <<= 1) {
            int v = (tid >= off) ? scan[tid - off] : 0;
            __syncthreads();
            scan[tid] += v;
            __syncthreads();
        }
        if (flag) {
            int pos = sbase + scan[tid] - 1;
            g_list[e][pos] = t; g_coefs[e][pos] = coef;
        }
        __syncthreads();
        if (tid == 0) sbase += scan[255];
        __syncthreads();
    }
    if (tid == 0) g_count[e] = sbase;
}
__global__ void offsets_kernel() {
    if (threadIdx.x == 0) {
        int r = 0;
#pragma unroll
        for (int e = 0; e < NE; e++) { g_off[e] = r; r += g_count[e]; }
    }
}

// ============================================================
// GEMM core (CTA 128M x 128N, BK=64, 512 thr, 16 warps 4x4, warp 32x32)
// ============================================================
struct GemmCtx {
    uint32_t aAddrH[2], arxH[2], aAddrL[2], arxL[2];
    uint32_t bAddrH[2], brxH[2], bAddrL[2], brxL[2];
    uint32_t a_cb, b_cb;
};
__device__ __forceinline__ void ctx_init(GemmCtx& C, uint32_t sb, int wm, int wn, int lane) {
#pragma unroll
    for (int mf = 0; mf < 2; mf++) {
        int r = wm * 32 + mf * 16 + (lane & 15);
        C.aAddrH[mf] = sb + SM_AH + ((uint32_t)r << 7);
        C.arxH[mf] = ((uint32_t)r & 7u) << 4;
        C.aAddrL[mf] = sb + SM_AL + (uint32_t)r * 64u;
        C.arxL[mf] = (((uint32_t)r >> 1) & 3u) << 4;
    }
#pragma unroll
    for (int g = 0; g < 2; g++) {
        int r = wn * 32 + g * 16 + ((lane >> 4) << 3) + (lane & 7);
        C.bAddrH[g] = sb + SM_BH + ((uint32_t)r << 7);
        C.brxH[g] = ((uint32_t)r & 7u) << 4;
        C.bAddrL[g] = sb + SM_BL + (uint32_t)r * 64u;
        C.brxL[g] = (((uint32_t)r >> 1) & 3u) << 4;
    }
    C.a_cb = (uint32_t)(lane >> 4) << 4;
    C.b_cb = ((uint32_t)(lane >> 3) & 1u) << 4;
}
__device__ __forceinline__ void mma_chunk(const GemmCtx& C, uint32_t bo,
                                          float accf[2][4][4], int acci[2][4][4]) {
#pragma unroll
    for (int ks = 0; ks < 4; ks++) {
        uint32_t acol = (uint32_t)ks * 32 + C.a_cb;
        uint32_t bcol = (uint32_t)ks * 32 + C.b_cb;
        uint32_t Ah[2][4], Bh[2][4];
#pragma unroll
        for (int mf = 0; mf < 2; mf++) LDSM_X4(Ah[mf], C.aAddrH[mf] + bo + (acol ^ C.arxH[mf]));
#pragma unroll
        for (int g = 0; g < 2; g++) LDSM_X4(Bh[g], C.bAddrH[g] + bo + (bcol ^ C.brxH[g]));
#pragma unroll
        for (int mf = 0; mf < 2; mf++)
#pragma unroll
            for (int nf = 0; nf < 4; nf++)
                MMAF16(accf[mf][nf], Ah[mf], Bh[nf >> 1][(nf & 1) * 2], Bh[nf >> 1][(nf & 1) * 2 + 1]);
    }
#pragma unroll
    for (int ki = 0; ki < 2; ki++) {
        uint32_t acol = (uint32_t)ki * 32 + C.a_cb;
        uint32_t bcol = (uint32_t)ki * 32 + C.b_cb;
        uint32_t Ai[2][4], Bi[2][4];
#pragma unroll
        for (int mf = 0; mf < 2; mf++) LDSM_X4(Ai[mf], C.aAddrL[mf] + bo + (acol ^ C.arxL[mf]));
#pragma unroll
        for (int g = 0; g < 2; g++) LDSM_X4(Bi[g], C.bAddrL[g] + bo + (bcol ^ C.brxL[g]));
#pragma unroll
        for (int mf = 0; mf < 2; mf++)
#pragma unroll
            for (int nf = 0; nf < 4; nf++)
                MMAI8(acci[mf][nf], Ai[mf], Bi[nf >> 1][(nf & 1) * 2], Bi[nf >> 1][(nf & 1) * 2 + 1]);
    }
}
__device__ __forceinline__ void b_fill(char* smem, int row, int tq, uint2 w8, int s, int smax) {
    uint32_t adj = 0x3800u + (uint32_t)((s - 127) << 10);
    int sh = s + 3 - smax;
    uint32_t hf[8], i8[4];
    uint32_t wv[2] = {w8.x, w8.y};
#pragma unroll
    for (int h = 0; h < 2; h++) {
#pragma unroll
        for (int b = 0; b < 4; b++) {
            uint32_t byte = (wv[h] >> (8 * b)) & 255u;
            hf[h * 4 + b] = dq16(byte, adj);
            uint32_t v = dqi8(byte & 15u, sh) | (dqi8(byte >> 4, sh) << 8);
            int idx = h * 4 + b;
            if (idx & 1) i8[idx >> 1] |= v << 16; else i8[idx >> 1] = v;
        }
    }
    uint32_t rxH = ((uint32_t)row & 7u) << 4;
    char* bh = smem + SM_BH + row * 128;
    *(uint4*)(bh + (((uint32_t)(tq * 32)) ^ rxH)) = make_uint4(hf[0], hf[1], hf[2], hf[3]);
    *(uint4*)(bh + (((uint32_t)(tq * 32 + 16)) ^ rxH)) = make_uint4(hf[4], hf[5], hf[6], hf[7]);
    uint32_t rxL = (((uint32_t)row >> 1) & 3u) << 4;
    *(uint4*)(smem + SM_BL + row * 64 + (((uint32_t)(tq * 16)) ^ rxL)) = make_uint4(i8[0], i8[1], i8[2], i8[3]);
}

// ============================================================
__global__ __launch_bounds__(512, 1) void gemm1_kernel(
    const int* __restrict__ gus, const float* __restrict__ gbias) {
    const int e  = blockIdx.y >> 6;
    const int r0 = (blockIdx.y & 63) << 7;
    const int m0 = blockIdx.x << 7;
    const int cnt = g_count[e];
    if (m0 >= cnt) return;
    const int valid = min(128, cnt - m0);
    const int off = g_off[e];
    extern __shared__ char smem[];
    const uint32_t sb = smem_u32(smem);
    const int tid = threadIdx.x, wid = tid >> 5, lane = tid & 31;
    const int wm = wid & 3, wn = wid >> 2;

    int* stok = (int*)(smem + SM_TOK);
    if (tid < 128) stok[tid] = g_list[e][m0 + (tid < valid ? tid : 0)];
    __syncthreads();

    const int arow = tid >> 2, q = tid & 3;
    const unsigned short* xh = g_x_h + (size_t)stok[arow] * D_HIDDEN;
    const char* xl = g_x_l + (size_t)stok[arow] * D_HIDDEN;
    const uint32_t arxH = ((uint32_t)arow & 7u) << 4;
    const uint32_t arxL = (((uint32_t)arow >> 1) & 3u) << 4;
    uint32_t foH[2], foL;
#pragma unroll
    for (int j = 0; j < 2; j++) foH[j] = ((uint32_t)arow << 7) + (((uint32_t)(q * 32 + j * 16)) ^ arxH);
    foL = (uint32_t)arow * 64u + (((uint32_t)(q * 16)) ^ arxL);
    const int brow = tid >> 2, tq = tid & 3;
    const int wrow = e * GU_ROWS + r0 + brow;
    const uint2* bw2 = (const uint2*)g_gu_pack + (size_t)wrow * 64;
    const int* scp = gus + (size_t)wrow * 32;
    const int smaxB = g_gu_smax[wrow];

    GemmCtx C; ctx_init(C, sb, wm, wn, lane);
    float accf[2][4][4]; int acci[2][4][4];
#pragma unroll
    for (int a = 0; a < 2; a++)
#pragma unroll
        for (int b = 0; b < 4; b++)
#pragma unroll
            for (int j = 0; j < 4; j++) { accf[a][b][j] = 0.0f; acci[a][b][j] = 0; }

    // prologue: A(0) async, B(0) regs
#pragma unroll
    for (int j = 0; j < 2; j++) CP16(sb + SM_AH + foH[j], xh + q * 16 + j * 8);
    CP16(sb + SM_AL + foL, xl + q * 16);
    CP_COMMIT();
    uint2 ub = bw2[tq];
    int s0 = scp[tq >> 1];

    const int NKB = D_HIDDEN / 64;
    for (int kb = 0; kb < NKB; kb++) {
        const uint32_t bo = (uint32_t)(kb & 1) * SM_BUF;
        b_fill(smem + bo, brow, tq, ub, s0, smaxB);
        CP_WAIT0();
        __syncthreads();
        if (kb + 1 < NKB) {
            const uint32_t bo2 = (uint32_t)((kb + 1) & 1) * SM_BUF;
#pragma unroll
            for (int j = 0; j < 2; j++) CP16(sb + bo2 + SM_AH + foH[j], xh + (kb + 1) * 64 + q * 16 + j * 8);
            CP16(sb + bo2 + SM_AL + foL, xl + (kb + 1) * 64 + q * 16);
            CP_COMMIT();
            ub = bw2[(kb + 1) * 4 + tq];
            s0 = scp[(kb + 1) * 2 + (tq >> 1)];
        }
        mma_chunk(C, bo, accf, acci);
    }
    __syncthreads();

    // epilogue: combine + SwiGLU -> stage f32 (128 x 64, stride 66) -> act hi + i8
    float* stage = (float*)smem;
#pragma unroll
    for (int mf = 0; mf < 2; mf++)
#pragma unroll
        for (int nf = 0; nf < 4; nf++) {
            int n0 = wn * 32 + nf * 8 + (lane & 3) * 2;
            int gcol = r0 + n0;
            int sg0 = g_gu_smax[e * GU_ROWS + gcol], sg1 = g_gu_smax[e * GU_ROWS + gcol + 1];
            float sc0 = __int_as_float((sg0 - 20) << 23);
            float sc1 = __int_as_float((sg1 - 20) << 23);
            float bg = gbias[(size_t)e * GU_ROWS + gcol], bu = gbias[(size_t)e * GU_ROWS + gcol + 1];
            int cl = wn * 16 + nf * 4 + (lane & 3);
#pragma unroll
            for (int rr = 0; rr < 2; rr++) {
                int r = wm * 32 + mf * 16 + (lane >> 2) + rr * 8;
                float gate = accf[mf][nf][rr * 2] + (float)acci[mf][nf][rr * 2] * sc0 + bg;
                float up   = accf[mf][nf][rr * 2 + 1] + (float)acci[mf][nf][rr * 2 + 1] * sc1 + bu;
                gate = fminf(gate, 7.0f);
                up = fminf(fmaxf(up, -7.0f), 7.0f);
                float sg = 1.0f / (1.0f + __expf(-1.702f * gate));
                stage[r * 66 + cl] = (up + 1.0f) * (gate * sg);
            }
        }
    __syncthreads();
    {
        int row = tid >> 2, seg = tid & 3;
        if (row < valid) {
            uint32_t hb[8], lb[4];
#pragma unroll
            for (int i = 0; i < 16; i += 2) {
                float v0 = stage[row * 66 + seg * 16 + i];
                float v1 = stage[row * 66 + seg * 16 + i + 1];
                __half h0 = __float2half_rn(v0), h1 = __float2half_rn(v1);
                hb[i >> 1] = (uint32_t)__half_as_ushort(h0) | ((uint32_t)__half_as_ushort(h1) << 16);
                int q0 = max(-127, min(127, __float2int_rn((v0 - __half2float(h0)) * 4096.0f)));
                int q1 = max(-127, min(127, __float2int_rn((v1 - __half2float(h1)) * 4096.0f)));
                uint32_t pp = ((uint32_t)q0 & 255u) | (((uint32_t)q1 & 255u) << 8);
                if (i & 2) lb[i >> 2] |= pp << 16; else lb[i >> 2] = pp;
            }
            size_t gb = (size_t)(off + m0 + row) * D_INTER + (r0 >> 1) + seg * 16;
            ((uint4*)(g_act_h + gb))[0] = make_uint4(hb[0], hb[1], hb[2], hb[3]);
            ((uint4*)(g_act_h + gb))[1] = make_uint4(hb[4], hb[5], hb[6], hb[7]);
            *(uint4*)(g_act_l + gb) = make_uint4(lb[0], lb[1], lb[2], lb[3]);
        }
    }
}

// ============================================================
__global__ __launch_bounds__(512, 1) void gemm2_kernel(
    const int* __restrict__ dns, const float* __restrict__ dbias,
    float* __restrict__ out) {
    const int e  = blockIdx.y >> 3;
    const int r0 = (blockIdx.y & 7) << 7;
    const int m0 = blockIdx.x << 7;
    const int cnt = g_count[e];
    if (m0 >= cnt) return;
    const int valid = min(128, cnt - m0);
    const int off = g_off[e];
    extern __shared__ char smem[];
    const uint32_t sb = smem_u32(smem);
    const int tid = threadIdx.x, wid = tid >> 5, lane = tid & 31;
    const int wm = wid & 3, wn = wid >> 2;

    int* stok = (int*)(smem + SM_TOK);
    float* scoef = (float*)(smem + SM_COEF);
    if (tid < 128) {
        int mm = (tid < valid) ? tid : 0;
        stok[tid] = g_list[e][m0 + mm];
        scoef[tid] = g_coefs[e][m0 + mm];
    }
    __syncthreads();

    const int arow = tid >> 2, q = tid & 3;
    const int pr = off + m0 + ((arow < valid) ? arow : 0);
    const unsigned short* ah = g_act_h + (size_t)pr * D_INTER;
    const char* al = g_act_l + (size_t)pr * D_INTER;
    const uint32_t arxH = ((uint32_t)arow & 7u) << 4;
    const uint32_t arxL = (((uint32_t)arow >> 1) & 3u) << 4;
    uint32_t foH[2], foL;
#pragma unroll
    for (int j = 0; j < 2; j++) foH[j] = ((uint32_t)arow << 7) + (((uint32_t)(q * 32 + j * 16)) ^ arxH);
    foL = (uint32_t)arow * 64u + (((uint32_t)(q * 16)) ^ arxL);
    const int brow = tid >> 2, tq = tid & 3;
    const int wrow = e * D_HIDDEN + r0 + brow;
    const uint2* bw2 = (const uint2*)g_dn_pack + (size_t)wrow * 256;
    const int* scp = dns + (size_t)wrow * 128;
    const int smaxB = g_dn_smax[wrow];

    GemmCtx C; ctx_init(C, sb, wm, wn, lane);
    float accf[2][4][4]; int acci[2][4][4];
#pragma unroll
    for (int a = 0; a < 2; a++)
#pragma unroll
        for (int b = 0; b < 4; b++)
#pragma unroll
            for (int j = 0; j < 4; j++) { accf[a][b][j] = 0.0f; acci[a][b][j] = 0; }

#pragma unroll
    for (int j = 0; j < 2; j++) CP16(sb + SM_AH + foH[j], ah + q * 16 + j * 8);
    CP16(sb + SM_AL + foL, al + q * 16);
    CP_COMMIT();
    uint2 ub = bw2[tq];
    int s0 = scp[tq >> 1];

    const int NKB = D_INTER / 64;
    for (int kb = 0; kb < NKB; kb++) {
        const uint32_t bo = (uint32_t)(kb & 1) * SM_BUF;
        b_fill(smem + bo, brow, tq, ub, s0, smaxB);
        CP_WAIT0();
        __syncthreads();
        if (kb + 1 < NKB) {
            const uint32_t bo2 = (uint32_t)((kb + 1) & 1) * SM_BUF;
#pragma unroll
            for (int j = 0; j < 2; j++) CP16(sb + bo2 + SM_AH + foH[j], ah + (kb + 1) * 64 + q * 16 + j * 8);
            CP16(sb + bo2 + SM_AL + foL, al + (kb + 1) * 64 + q * 16);
            CP_COMMIT();
            ub = bw2[(kb + 1) * 4 + tq];
            s0 = scp[(kb + 1) * 2 + (tq >> 1)];
        }
        mma_chunk(C, bo, accf, acci);
    }

    const float* db = dbias + (size_t)e * D_HIDDEN;
#pragma unroll
    for (int mf = 0; mf < 2; mf++)
#pragma unroll
        for (int nf = 0; nf < 4; nf++) {
            int gcol = r0 + wn * 32 + nf * 8 + (lane & 3) * 2;
            int sg0 = g_dn_smax[e * D_HIDDEN + gcol], sg1 = g_dn_smax[e * D_HIDDEN + gcol + 1];
            float sc0 = __int_as_float((sg0 - 16) << 23);
            float sc1 = __int_as_float((sg1 - 16) << 23);
            float b0 = db[gcol], b1 = db[gcol + 1];
#pragma unroll
            for (int rr = 0; rr < 2; rr++) {
                int m = wm * 32 + mf * 16 + (lane >> 2) + rr * 8;
                if (m < valid) {
                    float coef = scoef[m];
                    float* orow = out + (size_t)stok[m] * D_HIDDEN;
                    float v0 = accf[mf][nf][rr * 2] + (float)acci[mf][nf][rr * 2] * sc0 + b0;
                    float v1 = accf[mf][nf][rr * 2 + 1] + (float)acci[mf][nf][rr * 2 + 1] * sc1 + b1;
                    atomicAdd(orow + gcol, coef * v0);
                    atomicAdd(orow + gcol + 1, coef * v1);
                }
            }
        }
}

// ============================================================
extern "C" void kernel_launch(void* const* d_in, const int* in_sizes, int n_in,
                              void* d_out, int out_size) {
    const float* x     = (const float*)d_in[0];
    const float* rw    = (const float*)d_in[1];
    const float* rb    = (const float*)d_in[2];
    const float* gbias = (const float*)d_in[3];
    const float* dbias = (const float*)d_in[4];
    const int*   gub   = (const int*)d_in[5];
    const int*   gus   = (const int*)d_in[6];
    const int*   dnb   = (const int*)d_in[7];
    const int*   dns   = (const int*)d_in[8];
    float* out = (float*)d_out;

    cudaFuncSetAttribute(gemm1_kernel, cudaFuncAttributeMaxDynamicSharedMemorySize, SM_TOTAL);
    cudaFuncSetAttribute(gemm2_kernel, cudaFuncAttributeMaxDynamicSharedMemorySize, SM_TOTAL);
    uint4* gu_pack; cudaGetSymbolAddress((void**)&gu_pack, g_gu_pack);
    uint4* dn_pack; cudaGetSymbolAddress((void**)&dn_pack, g_dn_pack);
    int* gu_smax; cudaGetSymbolAddress((void**)&gu_smax, g_gu_smax);
    int* dn_smax; cudaGetSymbolAddress((void**)&dn_smax, g_dn_smax);

    zero_kernel<<<(out_size + 255) / 256, 256>>>(out, out_size);
    prep_x_kernel<<<NTOK, 256>>>(x);
    pack_kernel<<<8192, 256>>>(gub, gu_pack);
    pack_kernel<<<4096, 256>>>(dnb, dn_pack);
    smax_kernel<<<NE * GU_ROWS / 8, 256>>>(gus, gu_smax, 32);
    smax_kernel<<<NE * D_HIDDEN / 8, 256>>>(dns, dn_smax, 128);
    router_kernel<<<NTOK / 8, 256>>>(x, rw, rb);
    compact_kernel<<<NE, 256>>>();
    offsets_kernel<<<1, 32>>>();
    gemm1_kernel<<<dim3(16, NE * 64), 512, SM_TOTAL>>>(gus, gbias);
    gemm2_kernel<<<dim3(16, NE * 8), 512, SM_TOTAL>>>(dns, dbias, out);
}

// round 11
// speedup vs baseline: 1.3619x; 1.3619x over previous
#include <cuda_runtime.h>
#include <cuda_fp16.h>
#include <math.h>
#include <stdint.h>

#define D_HIDDEN 1024
#define D_INTER  4096
#define NE       8
#define NTOK     2048
#define NPAIR    (NTOK * 2)
#define GU_ROWS  8192

// per-buffer: AH 16K | AL 16K | B 16K ; two buffers (stride 48K)
#define SM_AH    0
#define SM_AL    16384
#define SM_BB    32768
#define SM_BUF   49152
#define SM_TOK   98304
#define SM_COEF  98816
#define SM_TOTAL 99328

__device__ __forceinline__ uint32_t smem_u32(const void* p) {
    uint32_t a;
    asm("{ .reg .u64 t; cvta.to.shared.u64 t, %1; cvt.u32.u64 %0, t; }" : "=r"(a) : "l"(p));
    return a;
}
#define LDSM_X4(r, addr) \
    asm volatile("ldmatrix.sync.aligned.m8n8.x4.shared.b16 {%0,%1,%2,%3}, [%4];" \
        : "=r"((r)[0]), "=r"((r)[1]), "=r"((r)[2]), "=r"((r)[3]) : "r"(addr))
#define MMAF16(c, a, b0, b1) \
    asm volatile("mma.sync.aligned.m16n8k16.row.col.f32.f16.f16.f32 " \
        "{%0,%1,%2,%3}, {%4,%5,%6,%7}, {%8,%9}, {%0,%1,%2,%3};" \
        : "+f"((c)[0]), "+f"((c)[1]), "+f"((c)[2]), "+f"((c)[3]) \
        : "r"((a)[0]), "r"((a)[1]), "r"((a)[2]), "r"((a)[3]), "r"(b0), "r"(b1))
#define CP16(dst, src) \
    asm volatile("cp.async.cg.shared.global [%0], [%1], 16;" :: "r"(dst), "l"(src))
#define CP_COMMIT() asm volatile("cp.async.commit_group;" ::: "memory")
#define CP_WAIT0()  asm volatile("cp.async.wait_group 0;" ::: "memory")

// fp4 pair -> packed fp16x2; adjc = 0x3800 + (s-127)<<10  (exact)
__device__ __forceinline__ uint32_t dq16(uint32_t byte, uint32_t adjc) {
    uint32_t n0 = byte & 15u, n1 = (byte >> 4) & 15u;
    uint32_t m0 = n0 & 7u, m1 = n1 & 7u;
    uint32_t b0 = (m0 == 0u) ? 0u : (adjc + ((m0 >= 2u) ? (m0 << 9) : 0u));
    uint32_t b1 = (m1 == 0u) ? 0u : (adjc + ((m1 >= 2u) ? (m1 << 9) : 0u));
    b0 |= (n0 & 8u) << 12;  b1 |= (n1 & 8u) << 12;
    return b0 | (b1 << 16);
}

__device__ int   g_top_idx[NTOK][2];
__device__ float g_top_w[NTOK][2];
__device__ int   g_count[NE];
__device__ int   g_off[NE];
__device__ int   g_list[NE][NTOK];
__device__ float g_coefs[NE][NTOK];
__device__ unsigned short g_x_h[(size_t)NTOK * D_HIDDEN];
__device__ unsigned short g_x_l[(size_t)NTOK * D_HIDDEN];
__device__ unsigned short g_act[(size_t)NPAIR * D_INTER];
__device__ uint4 g_gu_pack[(size_t)NE * GU_ROWS * 32];
__device__ uint4 g_dn_pack[(size_t)NE * D_HIDDEN * 128];

__global__ void zero_kernel(float* __restrict__ out, int n) {
    int i = blockIdx.x * blockDim.x + threadIdx.x;
    if (i < n) out[i] = 0.0f;
}
// x -> fp16 hi + fp16 residual planes
__global__ void prep_x_kernel(const float* __restrict__ x) {
    int row = blockIdx.x;
    int c = threadIdx.x * 4;
    float4 f = *(const float4*)(x + (size_t)row * D_HIDDEN + c);
    float v[4] = {f.x, f.y, f.z, f.w};
    unsigned short h[4], l[4];
#pragma unroll
    for (int i = 0; i < 4; i++) {
        __half hh = __float2half_rn(v[i]);
        h[i] = __half_as_ushort(hh);
        l[i] = __half_as_ushort(__float2half_rn(v[i] - __half2float(hh)));
    }
    uint2 ph, pl;
    ph.x = (uint32_t)h[0] | ((uint32_t)h[1] << 16); ph.y = (uint32_t)h[2] | ((uint32_t)h[3] << 16);
    pl.x = (uint32_t)l[0] | ((uint32_t)l[1] << 16); pl.y = (uint32_t)l[2] | ((uint32_t)l[3] << 16);
    *(uint2*)(g_x_h + (size_t)row * D_HIDDEN + c) = ph;
    *(uint2*)(g_x_l + (size_t)row * D_HIDDEN + c) = pl;
}
__global__ void pack_kernel(const int* __restrict__ src, uint4* __restrict__ dst) {
    size_t i = (size_t)blockIdx.x * 256 + threadIdx.x;
    const int4* s = (const int4*)src + i * 4;
    int4 a = s[0], b = s[1], c = s[2], d = s[3];
    uint4 o;
    o.x = (a.x & 255) | ((a.y & 255) << 8) | ((a.z & 255) << 16) | ((a.w & 255) << 24);
    o.y = (b.x & 255) | ((b.y & 255) << 8) | ((b.z & 255) << 16) | ((b.w & 255) << 24);
    o.z = (c.x & 255) | ((c.y & 255) << 8) | ((c.z & 255) << 16) | ((c.w & 255) << 24);
    o.w = (d.x & 255) | ((d.y & 255) << 8) | ((d.z & 255) << 16) | ((d.w & 255) << 24);
    dst[i] = o;
}
__global__ void router_kernel(const float* __restrict__ x,
                              const float* __restrict__ rw,
                              const float* __restrict__ rb) {
    int warp = threadIdx.x >> 5, lane = threadIdx.x & 31;
    int t = blockIdx.x * 8 + warp;
    if (t >= NTOK) return;
    float acc[NE];
#pragma unroll
    for (int e = 0; e < NE; e++) acc[e] = 0.0f;
    const float* xr = x + (size_t)t * D_HIDDEN;
    for (int k = lane; k < D_HIDDEN; k += 32) {
        float xv = xr[k];
#pragma unroll
        for (int e = 0; e < NE; e++) acc[e] += xv * rw[e * D_HIDDEN + k];
    }
#pragma unroll
    for (int e = 0; e < NE; e++)
#pragma unroll
        for (int o = 16; o > 0; o >>= 1) acc[e] += __shfl_xor_sync(0xffffffffu, acc[e], o);
    if (lane == 0) {
        float v[NE];
#pragma unroll
        for (int e = 0; e < NE; e++) v[e] = acc[e] + rb[e];
        int i0 = 0;
#pragma unroll
        for (int e = 1; e < NE; e++) if (v[e] > v[i0]) i0 = e;
        int i1 = -1;
#pragma unroll
        for (int e = 0; e < NE; e++) {
            if (e == i0) continue;
            if (i1 < 0 || v[e] > v[i1]) i1 = e;
        }
        float w1 = expf(v[i1] - v[i0]);
        float inv = 1.0f / (1.0f + w1);
        g_top_idx[t][0] = i0; g_top_idx[t][1] = i1;
        g_top_w[t][0] = inv;  g_top_w[t][1] = w1 * inv;
    }
}
__global__ void compact_kernel() {
    const int e = blockIdx.x, tid = threadIdx.x;
    __shared__ int scan[256];
    __shared__ int sbase;
    if (tid == 0) sbase = 0;
    __syncthreads();
    for (int c = 0; c < NTOK; c += 256) {
        int t = c + tid;
        int flag = (g_top_idx[t][0] == e) || (g_top_idx[t][1] == e);
        float coef = (g_top_idx[t][0] == e) ? g_top_w[t][0] : g_top_w[t][1];
        scan[tid] = flag;
        __syncthreads();
#pragma unroll
        for (int off = 1; off < 256; off <<= 1) {
            int v = (tid >= off) ? scan[tid - off] : 0;
            __syncthreads();
            scan[tid] += v;
            __syncthreads();
        }
        if (flag) {
            int pos = sbase + scan[tid] - 1;
            g_list[e][pos] = t; g_coefs[e][pos] = coef;
        }
        __syncthreads();
        if (tid == 0) sbase += scan[255];
        __syncthreads();
    }
    if (tid == 0) g_count[e] = sbase;
}
__global__ void offsets_kernel() {
    if (threadIdx.x == 0) {
        int r = 0;
#pragma unroll
        for (int e = 0; e < NE; e++) { g_off[e] = r; r += g_count[e]; }
    }
}

// ============================================================
// GEMM1 (fp16 hi+lo planes, exact). 128x128 tile, BK=64,
// 8 warps (4M x 2N), warp 32x64, double-buffered cp.async.
// ============================================================
__global__ __launch_bounds__(256, 2) void gemm1_kernel(
    const int* __restrict__ gus, const float* __restrict__ gbias) {
    const int e  = blockIdx.y >> 6;
    const int r0 = (blockIdx.y & 63) << 7;
    const int m0 = blockIdx.x << 7;
    const int cnt = g_count[e];
    if (m0 >= cnt) return;
    const int valid = min(128, cnt - m0);
    const int off = g_off[e];
    extern __shared__ char smem[];
    const uint32_t sb = smem_u32(smem);
    const int tid = threadIdx.x, wid = tid >> 5, lane = tid & 31;
    const int wm = wid & 3, wn = wid >> 2;

    int* stok = (int*)(smem + SM_TOK);
    if (tid < 128) stok[tid] = g_list[e][m0 + (tid < valid ? tid : 0)];
    __syncthreads();

    const int arow = tid >> 1, kh = (tid & 1) << 5;
    const unsigned short* xh = g_x_h + (size_t)stok[arow] * D_HIDDEN + kh;
    const unsigned short* xl = g_x_l + (size_t)stok[arow] * D_HIDDEN + kh;
    const uint4* bw = g_gu_pack + (size_t)(e * GU_ROWS + r0 + arow) * 32;
    const int*  sc = gus + (size_t)(e * GU_ROWS + r0 + arow) * 32;
    const uint32_t fbase = (uint32_t)arow << 7;
    const uint32_t frx = ((uint32_t)arow & 7u) << 4;
    uint32_t fo[4];
#pragma unroll
    for (int j = 0; j < 4; j++)
        fo[j] = fbase + ((((uint32_t)(kh + j * 8)) << 1) ^ frx);

    uint32_t aAddr[2], arx[2];
#pragma unroll
    for (int mf = 0; mf < 2; mf++) {
        int r = wm * 32 + mf * 16 + (lane & 15);
        aAddr[mf] = sb + ((uint32_t)r << 7);
        arx[mf] = ((uint32_t)r & 7u) << 4;
    }
    const uint32_t a_cb = (uint32_t)(lane >> 4) << 4;
    uint32_t bAddr[4], brxv[4];
#pragma unroll
    for (int g = 0; g < 4; g++) {
        int r = wn * 64 + g * 16 + ((lane >> 4) << 3) + (lane & 7);
        bAddr[g] = sb + SM_BB + ((uint32_t)r << 7);
        brxv[g] = ((uint32_t)r & 7u) << 4;
    }
    const uint32_t b_cb = ((uint32_t)(lane >> 3) & 1u) << 4;

    float acc[2][8][4];
#pragma unroll
    for (int mf = 0; mf < 2; mf++)
#pragma unroll
        for (int nf = 0; nf < 8; nf++)
#pragma unroll
            for (int j = 0; j < 4; j++) acc[mf][nf][j] = 0.0f;

#pragma unroll
    for (int j = 0; j < 4; j++) {
        CP16(sb + SM_AH + fo[j], xh + j * 8);
        CP16(sb + SM_AL + fo[j], xl + j * 8);
    }
    CP_COMMIT();
    uint4 ub = bw[tid & 1];
    uint32_t adj = 0x3800u + (uint32_t)((sc[tid & 1] - 127) << 10);

    const int NKB = D_HIDDEN / 64;
    for (int kb = 0; kb < NKB; kb++) {
        const uint32_t bo = (uint32_t)(kb & 1) * SM_BUF;
        {
            uint32_t w4[4] = {ub.x, ub.y, ub.z, ub.w};
#pragma unroll
            for (int q = 0; q < 4; q++) {
                uint32_t ww = w4[q];
                uint4 r;
                r.x = dq16(ww & 255u, adj);
                r.y = dq16((ww >> 8) & 255u, adj);
                r.z = dq16((ww >> 16) & 255u, adj);
                r.w = dq16(ww >> 24, adj);
                *(uint4*)(smem + bo + SM_BB + fo[q]) = r;
            }
        }
        CP_WAIT0();
        __syncthreads();
        if (kb + 1 < NKB) {
            const uint32_t bo2 = (uint32_t)((kb + 1) & 1) * SM_BUF;
#pragma unroll
            for (int j = 0; j < 4; j++) {
                CP16(sb + bo2 + SM_AH + fo[j], xh + (kb + 1) * 64 + j * 8);
                CP16(sb + bo2 + SM_AL + fo[j], xl + (kb + 1) * 64 + j * 8);
            }
            CP_COMMIT();
            int bin = (kb + 1) * 2 + (tid & 1);
            ub = bw[bin];
            adj = 0x3800u + (uint32_t)((sc[bin] - 127) << 10);
        }
#pragma unroll
        for (int ks = 0; ks < 4; ks++) {
            uint32_t acol = (uint32_t)ks * 32 + a_cb;
            uint32_t bcol = (uint32_t)ks * 32 + b_cb;
            uint32_t Ah[2][4], Al[2][4], Bf[4][4];
#pragma unroll
            for (int mf = 0; mf < 2; mf++) {
                LDSM_X4(Ah[mf], aAddr[mf] + bo + SM_AH + (acol ^ arx[mf]));
                LDSM_X4(Al[mf], aAddr[mf] + bo + SM_AL + (acol ^ arx[mf]));
            }
#pragma unroll
            for (int g = 0; g < 4; g++) LDSM_X4(Bf[g], bAddr[g] + bo + (bcol ^ brxv[g]));
#pragma unroll
            for (int mf = 0; mf < 2; mf++)
#pragma unroll
                for (int nf = 0; nf < 8; nf++) {
                    uint32_t bb0 = Bf[nf >> 1][(nf & 1) * 2];
                    uint32_t bb1 = Bf[nf >> 1][(nf & 1) * 2 + 1];
                    MMAF16(acc[mf][nf], Ah[mf], bb0, bb1);
                    MMAF16(acc[mf][nf], Al[mf], bb0, bb1);
                }
        }
    }
    __syncthreads();

    // epilogue: bias + SwiGLU -> stage -> single fp16 act plane
    const float* gb = gbias + (size_t)e * GU_ROWS;
    unsigned short* stage = (unsigned short*)smem;
#pragma unroll
    for (int mf = 0; mf < 2; mf++)
#pragma unroll
        for (int nf = 0; nf < 8; nf++) {
            int gucol = r0 + wn * 64 + nf * 8 + (lane & 3) * 2;
            float bg = gb[gucol], bu = gb[gucol + 1];
            int cl = wn * 32 + nf * 4 + (lane & 3);
#pragma unroll
            for (int rr = 0; rr < 2; rr++) {
                int r = wm * 32 + mf * 16 + (lane >> 2) + rr * 8;
                float gate = acc[mf][nf][rr * 2 + 0] + bg;
                float up   = acc[mf][nf][rr * 2 + 1] + bu;
                gate = fminf(gate, 7.0f);
                up = fminf(fmaxf(up, -7.0f), 7.0f);
                float sg = 1.0f / (1.0f + __expf(-1.702f * gate));
                float a = (up + 1.0f) * (gate * sg);
                stage[r * 72 + cl] = __half_as_ushort(__float2half_rn(a));
            }
        }
    __syncthreads();
    {
        int row = tid >> 1;
        if (row < valid) {
            size_t gbase = (size_t)(off + m0 + row) * D_INTER + (r0 >> 1) + (tid & 1) * 32;
            uint4* dh = (uint4*)(g_act + gbase);
            const uint4* shp = (const uint4*)(stage + row * 72 + (tid & 1) * 32);
#pragma unroll
            for (int i = 0; i < 4; i++) dh[i] = shp[i];
        }
    }
}

// ============================================================
// GEMM2 (single fp16 plane). Same tile; half the MMAs.
// ============================================================
__global__ __launch_bounds__(256, 2) void gemm2_kernel(
    const int* __restrict__ dns, const float* __restrict__ dbias,
    float* __restrict__ out) {
    const int e  = blockIdx.y >> 3;
    const int r0 = (blockIdx.y & 7) << 7;
    const int m0 = blockIdx.x << 7;
    const int cnt = g_count[e];
    if (m0 >= cnt) return;
    const int valid = min(128, cnt - m0);
    const int off = g_off[e];
    extern __shared__ char smem[];
    const uint32_t sb = smem_u32(smem);
    const int tid = threadIdx.x, wid = tid >> 5, lane = tid & 31;
    const int wm = wid & 3, wn = wid >> 2;

    int* stok = (int*)(smem + SM_TOK);
    float* scoef = (float*)(smem + SM_COEF);
    if (tid < 128) {
        int mm = (tid < valid) ? tid : 0;
        stok[tid] = g_list[e][m0 + mm];
        scoef[tid] = g_coefs[e][m0 + mm];
    }
    __syncthreads();

    const int arow = tid >> 1, kh = (tid & 1) << 5;
    const int pr = off + m0 + ((arow < valid) ? arow : 0);
    const unsigned short* ah = g_act + (size_t)pr * D_INTER + kh;
    const uint4* bw = g_dn_pack + (size_t)(e * D_HIDDEN + r0 + arow) * 128;
    const int*  sc = dns + (size_t)(e * D_HIDDEN + r0 + arow) * 128;
    const uint32_t fbase = (uint32_t)arow << 7;
    const uint32_t frx = ((uint32_t)arow & 7u) << 4;
    uint32_t fo[4];
#pragma unroll
    for (int j = 0; j < 4; j++)
        fo[j] = fbase + ((((uint32_t)(kh + j * 8)) << 1) ^ frx);

    uint32_t aAddr[2], arx[2];
#pragma unroll
    for (int mf = 0; mf < 2; mf++) {
        int r = wm * 32 + mf * 16 + (lane & 15);
        aAddr[mf] = sb + ((uint32_t)r << 7);
        arx[mf] = ((uint32_t)r & 7u) << 4;
    }
    const uint32_t a_cb = (uint32_t)(lane >> 4) << 4;
    uint32_t bAddr[4], brxv[4];
#pragma unroll
    for (int g = 0; g < 4; g++) {
        int r = wn * 64 + g * 16 + ((lane >> 4) << 3) + (lane & 7);
        bAddr[g] = sb + SM_BB + ((uint32_t)r << 7);
        brxv[g] = ((uint32_t)r & 7u) << 4;
    }
    const uint32_t b_cb = ((uint32_t)(lane >> 3) & 1u) << 4;

    float acc[2][8][4];
#pragma unroll
    for (int mf = 0; mf < 2; mf++)
#pragma unroll
        for (int nf = 0; nf < 8; nf++)
#pragma unroll
            for (int j = 0; j < 4; j++) acc[mf][nf][j] = 0.0f;

#pragma unroll
    for (int j = 0; j < 4; j++) CP16(sb + SM_AH + fo[j], ah + j * 8);
    CP_COMMIT();
    uint4 ub = bw[tid & 1];
    uint32_t adj = 0x3800u + (uint32_t)((sc[tid & 1] - 127) << 10);

    const int NKB = D_INTER / 64;
    for (int kb = 0; kb < NKB; kb++) {
        const uint32_t bo = (uint32_t)(kb & 1) * SM_BUF;
        {
            uint32_t w4[4] = {ub.x, ub.y, ub.z, ub.w};
#pragma unroll
            for (int q = 0; q < 4; q++) {
                uint32_t ww = w4[q];
                uint4 r;
                r.x = dq16(ww & 255u, adj);
                r.y = dq16((ww >> 8) & 255u, adj);
                r.z = dq16((ww >> 16) & 255u, adj);
                r.w = dq16(ww >> 24, adj);
                *(uint4*)(smem + bo + SM_BB + fo[q]) = r;
            }
        }
        CP_WAIT0();
        __syncthreads();
        if (kb + 1 < NKB) {
            const uint32_t bo2 = (uint32_t)((kb + 1) & 1) * SM_BUF;
#pragma unroll
            for (int j = 0; j < 4; j++)
                CP16(sb + bo2 + SM_AH + fo[j], ah + (kb + 1) * 64 + j * 8);
            CP_COMMIT();
            int bin = (kb + 1) * 2 + (tid & 1);
            ub = bw[bin];
            adj = 0x3800u + (uint32_t)((sc[bin] - 127) << 10);
        }
#pragma unroll
        for (int ks = 0; ks < 4; ks++) {
            uint32_t acol = (uint32_t)ks * 32 + a_cb;
            uint32_t bcol = (uint32_t)ks * 32 + b_cb;
            uint32_t Ah[2][4], Bf[4][4];
#pragma unroll
            for (int mf = 0; mf < 2; mf++)
                LDSM_X4(Ah[mf], aAddr[mf] + bo + SM_AH + (acol ^ arx[mf]));
#pragma unroll
            for (int g = 0; g < 4; g++) LDSM_X4(Bf[g], bAddr[g] + bo + (bcol ^ brxv[g]));
#pragma unroll
            for (int mf = 0; mf < 2; mf++)
#pragma unroll
                for (int nf = 0; nf < 8; nf++) {
                    uint32_t bb0 = Bf[nf >> 1][(nf & 1) * 2];
                    uint32_t bb1 = Bf[nf >> 1][(nf & 1) * 2 + 1];
                    MMAF16(acc[mf][nf], Ah[mf], bb0, bb1);
                }
        }
    }

    const float* db = dbias + (size_t)e * D_HIDDEN;
#pragma unroll
    for (int mf = 0; mf < 2; mf++)
#pragma unroll
        for (int nf = 0; nf < 8; nf++) {
            int gcol = r0 + wn * 64 + nf * 8 + (lane & 3) * 2;
            float b0 = db[gcol], b1 = db[gcol + 1];
#pragma unroll
            for (int rr = 0; rr < 2; rr++) {
                int m = wm * 32 + mf * 16 + (lane >> 2) + rr * 8;
                if (m < valid) {
                    float coef = scoef[m];
                    float* orow = out + (size_t)stok[m] * D_HIDDEN;
                    atomicAdd(orow + gcol,     coef * (acc[mf][nf][rr * 2 + 0] + b0));
                    atomicAdd(orow + gcol + 1, coef * (acc[mf][nf][rr * 2 + 1] + b1));
                }
            }
        }
}

// ============================================================
extern "C" void kernel_launch(void* const* d_in, const int* in_sizes, int n_in,
                              void* d_out, int out_size) {
    const float* x     = (const float*)d_in[0];
    const float* rw    = (const float*)d_in[1];
    const float* rb    = (const float*)d_in[2];
    const float* gbias = (const float*)d_in[3];
    const float* dbias = (const float*)d_in[4];
    const int*   gub   = (const int*)d_in[5];
    const int*   gus   = (const int*)d_in[6];
    const int*   dnb   = (const int*)d_in[7];
    const int*   dns   = (const int*)d_in[8];
    float* out = (float*)d_out;

    cudaFuncSetAttribute(gemm1_kernel, cudaFuncAttributeMaxDynamicSharedMemorySize, SM_TOTAL);
    cudaFuncSetAttribute(gemm2_kernel, cudaFuncAttributeMaxDynamicSharedMemorySize, SM_TOTAL);
    uint4* gu_pack; cudaGetSymbolAddress((void**)&gu_pack, g_gu_pack);
    uint4* dn_pack; cudaGetSymbolAddress((void**)&dn_pack, g_dn_pack);

    zero_kernel<<<(out_size + 255) / 256, 256>>>(out, out_size);
    prep_x_kernel<<<NTOK, 256>>>(x);
    pack_kernel<<<8192, 256>>>(gub, gu_pack);
    pack_kernel<<<4096, 256>>>(dnb, dn_pack);
    router_kernel<<<NTOK / 8, 256>>>(x, rw, rb);
    compact_kernel<<<NE, 256>>>();
    offsets_kernel<<<1, 32>>>();
    gemm1_kernel<<<dim3(16, NE * 64), 256, SM_TOTAL>>>(gus, gbias);
    gemm2_kernel<<<dim3(16, NE * 8), 256, SM_TOTAL>>>(dns, dbias, out);
}